// round 6
// baseline (speedup 1.0000x reference)
#include <cuda_runtime.h>
#include <cuda_bf16.h>
#include <math.h>
#include <cstdint>

// ===========================================================================
// Fused MLP via mma.sync HMMA bf16 hi/lo split (fp32-grade accuracy):
//   prep_x : x fp32 -> x_hi/x_lo bf16 [65536,384] (+ row stats)
//   prep_w : W1/W2/W3 -> transposed [N,Kpad] bf16 hi/lo
//   gemm<L>: 512-thr CTA, tile M=128 x N=256 (128 for L3), warp tile 32x64,
//            K-chunk 32, 3-stage cp.async pipeline, ONE barrier per chunk.
//   head   : stats@Ws -> concat -> C1,C2,C3 -> sigmoid
// ===========================================================================

#define MTOT 65536

// ---------------- device scratch -------------------------------------------
__device__ __nv_bfloat16 g_xh[(size_t)MTOT * 384];
__device__ __nv_bfloat16 g_xl[(size_t)MTOT * 384];
__device__ __nv_bfloat16 g_w1h[512 * 384], g_w1l[512 * 384];
__device__ __nv_bfloat16 g_w2h[256 * 512], g_w2l[256 * 512];
__device__ __nv_bfloat16 g_w3h[128 * 256], g_w3l[128 * 256];
__device__ __nv_bfloat16 g_h1h[(size_t)MTOT * 512], g_h1l[(size_t)MTOT * 512];
__device__ __nv_bfloat16 g_h2h[(size_t)MTOT * 256], g_h2l[(size_t)MTOT * 256];
__device__ float g_h3[(size_t)MTOT * 128];
__device__ float g_stats[(size_t)MTOT * 8];

// ---------------- helpers --------------------------------------------------
__device__ __forceinline__ uint32_t smem_to_u32(const void* p) {
    uint32_t a;
    asm("{ .reg .u64 t; cvta.to.shared.u64 t, %1; cvt.u32.u64 %0, t; }"
        : "=r"(a) : "l"(p));
    return a;
}
__device__ __forceinline__ void ldsm4(uint32_t* r, uint32_t addr) {
    asm volatile("ldmatrix.sync.aligned.m8n8.x4.shared.b16 {%0,%1,%2,%3}, [%4];"
        : "=r"(r[0]), "=r"(r[1]), "=r"(r[2]), "=r"(r[3]) : "r"(addr));
}
__device__ __forceinline__ void mma16816(float* c, const uint32_t* a,
                                         const uint32_t* b) {
    asm volatile(
        "mma.sync.aligned.m16n8k16.row.col.f32.bf16.bf16.f32 "
        "{%0,%1,%2,%3}, {%4,%5,%6,%7}, {%8,%9}, {%0,%1,%2,%3};"
        : "+f"(c[0]), "+f"(c[1]), "+f"(c[2]), "+f"(c[3])
        : "r"(a[0]), "r"(a[1]), "r"(a[2]), "r"(a[3]), "r"(b[0]), "r"(b[1]));
}
__device__ __forceinline__ void cp_async16(uint32_t dst, const void* src) {
    asm volatile("cp.async.cg.shared.global [%0], [%1], 16;"
        :: "r"(dst), "l"(src));
}
#define CP_COMMIT() asm volatile("cp.async.commit_group;" ::: "memory")
#define CP_WAIT(n)  asm volatile("cp.async.wait_group %0;" :: "n"(n) : "memory")

__device__ __forceinline__ void split_bf16(float v, __nv_bfloat16& hi,
                                           __nv_bfloat16& lo) {
    hi = __float2bfloat16(v);
    lo = __float2bfloat16(v - __bfloat162float(hi));
}
__device__ __forceinline__ uint32_t pack_bf16x2(__nv_bfloat16 a, __nv_bfloat16 b) {
    __nv_bfloat162 t; t.x = a; t.y = b;
    return *(uint32_t*)&t;
}

// ---------------- prep_x: split x + row stats ------------------------------
__global__ __launch_bounds__(256)
void prep_x_kernel(const float* __restrict__ x) {
    const int warp = threadIdx.x >> 5, lane = threadIdx.x & 31;
    const int r = blockIdx.x * 8 + warp;
    const float* xr = x + (size_t)r * 365;

    float v[12];
    float s = 0.f, mn = 3.4e38f, mx = -3.4e38f;
#pragma unroll
    for (int i = 0; i < 12; i++) {
        int k = lane + 32 * i;
        bool ok = k < 365;
        v[i] = ok ? xr[k] : 0.f;
        if (ok) { s += v[i]; mn = fminf(mn, v[i]); mx = fmaxf(mx, v[i]); }
    }
#pragma unroll
    for (int o = 16; o; o >>= 1) {
        s += __shfl_xor_sync(0xffffffffu, s, o);
        mn = fminf(mn, __shfl_xor_sync(0xffffffffu, mn, o));
        mx = fmaxf(mx, __shfl_xor_sync(0xffffffffu, mx, o));
    }
    const float mu = s * (1.0f / 365.0f);
    float s2 = 0.f, s3 = 0.f, s4 = 0.f;
#pragma unroll
    for (int i = 0; i < 12; i++) {
        int k = lane + 32 * i;
        if (k < 365) {
            float c = v[i] - mu, c2 = c * c;
            s2 += c2; s3 += c2 * c; s4 += c2 * c2;
        }
    }
#pragma unroll
    for (int o = 16; o; o >>= 1) {
        s2 += __shfl_xor_sync(0xffffffffu, s2, o);
        s3 += __shfl_xor_sync(0xffffffffu, s3, o);
        s4 += __shfl_xor_sync(0xffffffffu, s4, o);
    }
    if (lane == 0) {
        float var1 = s2 * (1.0f / 364.0f);
        float sig = sqrtf(var1);
        float m3 = s3 * (1.0f / 365.0f);
        float m4 = s4 * (1.0f / 365.0f);
        float sig2 = sig * sig;
        float* st = g_stats + (size_t)r * 8;
        st[0] = mu; st[1] = sig; st[2] = mn; st[3] = mx;
        st[4] = m3 / (sig * sig2 + 1e-8f);
        st[5] = m4 / (sig2 * sig2 + 1e-8f);
    }
#pragma unroll
    for (int i = 0; i < 12; i++) {
        int k = lane + 32 * i;
        float val = (k < 365) ? v[i] : 0.f;
        __nv_bfloat16 hi, lo;
        split_bf16(val, hi, lo);
        g_xh[(size_t)r * 384 + k] = hi;
        g_xl[(size_t)r * 384 + k] = lo;
    }
}

// ---------------- prep_w ----------------------------------------------------
#define W1T_ELEMS (512 * 384)
#define W2T_ELEMS (256 * 512)
#define W3T_ELEMS (128 * 256)
#define WT_TOTAL  (W1T_ELEMS + W2T_ELEMS + W3T_ELEMS)

__global__ __launch_bounds__(256)
void prep_w_kernel(const float* __restrict__ W1, const float* __restrict__ W2,
                   const float* __restrict__ W3) {
    int idx = blockIdx.x * 256 + threadIdx.x;
    if (idx >= WT_TOTAL) return;
    float v; __nv_bfloat16 hi, lo;
    if (idx < W1T_ELEMS) {
        int n = idx / 384, k = idx % 384;
        v = (k < 365) ? W1[(size_t)k * 512 + n] : 0.f;
        split_bf16(v, hi, lo);
        g_w1h[idx] = hi; g_w1l[idx] = lo;
    } else if (idx < W1T_ELEMS + W2T_ELEMS) {
        int j = idx - W1T_ELEMS;
        int n = j / 512, k = j % 512;
        v = W2[(size_t)k * 256 + n];
        split_bf16(v, hi, lo);
        g_w2h[j] = hi; g_w2l[j] = lo;
    } else {
        int j = idx - W1T_ELEMS - W2T_ELEMS;
        int n = j / 256, k = j % 256;
        v = W3[(size_t)k * 128 + n];
        split_bf16(v, hi, lo);
        g_w3h[j] = hi; g_w3l[j] = lo;
    }
}

// ---------------- HMMA GEMM: 3-stage cp.async, 1 barrier/chunk -------------
// K-chunk = 32 (row = 64B data + 16B pad = 80B stride; 5 coprime 8 -> no
// ldmatrix bank conflicts).
template <int LAYER>
__global__ __launch_bounds__(512, 1)
void gemm_hmma_kernel(const float* __restrict__ bias) {
    constexpr int KPAD  = (LAYER == 1) ? 384 : (LAYER == 2) ? 512 : 256;
    constexpr int BLK_N = (LAYER == 3) ? 128 : 256;
    constexpr int OUTLD = (LAYER == 1) ? 512 : (LAYER == 2) ? 256 : 128;
    constexpr int KB    = KPAD / 32;
    constexpr bool SPLIT = (LAYER != 3);
    constexpr int LDSB  = 80;
    constexpr int WARP_N = BLK_N / 4;        // 64 or 32
    constexpr int NWT    = WARP_N / 16;      // 4 or 2
    constexpr int NT     = 2 * NWT;

    // per-stage buffer layout (bytes)
    constexpr uint32_t A_HI = 0;
    constexpr uint32_t A_LO = 128 * LDSB;                 // 10240
    constexpr uint32_t B_HI = 2 * 128 * LDSB;             // 20480
    constexpr uint32_t B_LO = B_HI + BLK_N * LDSB;
    constexpr uint32_t SBUF = B_HI + 2 * BLK_N * LDSB;    // 61440 / 40960

    const __nv_bfloat16* Ah_g = (LAYER == 1) ? g_xh  : (LAYER == 2) ? g_h1h : g_h2h;
    const __nv_bfloat16* Al_g = (LAYER == 1) ? g_xl  : (LAYER == 2) ? g_h1l : g_h2l;
    const __nv_bfloat16* Bh_g = (LAYER == 1) ? g_w1h : (LAYER == 2) ? g_w2h : g_w3h;
    const __nv_bfloat16* Bl_g = (LAYER == 1) ? g_w1l : (LAYER == 2) ? g_w2l : g_w3l;
    __nv_bfloat16* Oh = (LAYER == 1) ? g_h1h : g_h2h;
    __nv_bfloat16* Ol = (LAYER == 1) ? g_h1l : g_h2l;

    extern __shared__ char smem[];
    const uint32_t sb = smem_to_u32(smem);

    const int tid = threadIdx.x, warp = tid >> 5, lane = tid & 31;
    const int row0 = blockIdx.x * 128;
    const int nbase = blockIdx.y * BLK_N;
    const int wm = (warp & 3) * 32;
    const int wn = (warp >> 2) * WARP_N;

    float acc[2][NT][4];
#pragma unroll
    for (int mt = 0; mt < 2; mt++)
#pragma unroll
        for (int t = 0; t < NT; t++)
#pragma unroll
            for (int j = 0; j < 4; j++) acc[mt][t][j] = 0.f;

    const uint32_t a_off = (uint32_t)(wm + (lane & 15)) * LDSB + ((lane >> 4) * 16);
    const uint32_t b_off = (uint32_t)(wn + (lane & 7) + ((lane >> 4) << 3)) * LDSB
                           + (((lane >> 3) & 1) * 16);

    // one 32-K chunk: A hi+lo = 1024 granules (16B), B hi+lo = BLK_N*8 granules
    auto load_chunk = [&](int kb, int buf) {
        const uint32_t bb = sb + (uint32_t)buf * SBUF;
        {
            const size_t abase = (size_t)row0 * KPAD + kb * 32;
            const int r = tid >> 2, g = tid & 3;       // 512 threads = 512 granules
            const size_t src = abase + (size_t)r * KPAD + g * 8;
            const uint32_t dst = bb + r * LDSB + g * 16;
            cp_async16(dst + A_HI, Ah_g + src);
            cp_async16(dst + A_LO, Al_g + src);
        }
        const size_t bbase = (size_t)nbase * KPAD + kb * 32;
#pragma unroll
        for (int it = 0; it < BLK_N / 128; it++) {
            const int idx = tid + it * 512;
            const int n = idx >> 2, g = idx & 3;
            const size_t src = bbase + (size_t)n * KPAD + g * 8;
            const uint32_t dst = bb + B_HI + n * LDSB + g * 16;
            cp_async16(dst, Bh_g + src);
            cp_async16(dst + (B_LO - B_HI), Bl_g + src);
        }
    };

    // prologue: two chunks in flight
    load_chunk(0, 0); CP_COMMIT();
    load_chunk(1, 1); CP_COMMIT();

    for (int kb = 0; kb < KB; kb++) {
        if (kb + 1 < KB) { CP_WAIT(1); } else { CP_WAIT(0); }
        __syncthreads();
        if (kb + 2 < KB) { load_chunk(kb + 2, (kb + 2) % 3); CP_COMMIT(); }

        const uint32_t bb = sb + (uint32_t)(kb % 3) * SBUF;
#pragma unroll
        for (int ks = 0; ks < 2; ks++) {
            uint32_t ah[2][4], al[2][4];
#pragma unroll
            for (int mt = 0; mt < 2; mt++) {
                const uint32_t ao = a_off + mt * (16 * LDSB) + ks * 32;
                ldsm4(ah[mt], bb + A_HI + ao);
                ldsm4(al[mt], bb + A_LO + ao);
            }
#pragma unroll
            for (int t = 0; t < NWT; t++) {
                uint32_t bh[4], bl[4];
                const uint32_t bo = b_off + t * (16 * LDSB) + ks * 32;
                ldsm4(bh, bb + B_HI + bo);
                ldsm4(bl, bb + B_LO + bo);
#pragma unroll
                for (int mt = 0; mt < 2; mt++) {
                    // interleave the two acc chains to shorten RAW chains
                    mma16816(acc[mt][2 * t],     ah[mt], bh);
                    mma16816(acc[mt][2 * t + 1], ah[mt], bh + 2);
                    mma16816(acc[mt][2 * t],     ah[mt], bl);
                    mma16816(acc[mt][2 * t + 1], ah[mt], bl + 2);
                    mma16816(acc[mt][2 * t],     al[mt], bh);
                    mma16816(acc[mt][2 * t + 1], al[mt], bh + 2);
                }
            }
        }
    }

    // ---- epilogue: bias + relu (+ split) ----
#pragma unroll
    for (int mt = 0; mt < 2; mt++) {
        const int r0 = row0 + wm + mt * 16 + (lane >> 2);
        const int r1 = r0 + 8;
#pragma unroll
        for (int t = 0; t < NT; t++) {
            const int ncol = wn + t * 8 + (lane & 3) * 2;
            const float b0 = bias[nbase + ncol];
            const float b1 = bias[nbase + ncol + 1];
            float d0 = fmaxf(acc[mt][t][0] + b0, 0.f);
            float d1 = fmaxf(acc[mt][t][1] + b1, 0.f);
            float d2 = fmaxf(acc[mt][t][2] + b0, 0.f);
            float d3 = fmaxf(acc[mt][t][3] + b1, 0.f);
            if (SPLIT) {
                __nv_bfloat16 h0, l0, h1, l1;
                split_bf16(d0, h0, l0); split_bf16(d1, h1, l1);
                *(uint32_t*)(Oh + (size_t)r0 * OUTLD + nbase + ncol) = pack_bf16x2(h0, h1);
                *(uint32_t*)(Ol + (size_t)r0 * OUTLD + nbase + ncol) = pack_bf16x2(l0, l1);
                split_bf16(d2, h0, l0); split_bf16(d3, h1, l1);
                *(uint32_t*)(Oh + (size_t)r1 * OUTLD + nbase + ncol) = pack_bf16x2(h0, h1);
                *(uint32_t*)(Ol + (size_t)r1 * OUTLD + nbase + ncol) = pack_bf16x2(l0, l1);
            } else {
                *(float2*)(g_h3 + (size_t)r0 * OUTLD + nbase + ncol) = make_float2(d0, d1);
                *(float2*)(g_h3 + (size_t)r1 * OUTLD + nbase + ncol) = make_float2(d2, d3);
            }
        }
    }
}

// ---------------- head ------------------------------------------------------
template <int RM, int U, bool RELU>
__device__ __forceinline__ void gemm_scalar(const float* __restrict__ As, int lda,
                                            const float* __restrict__ W,
                                            const float* __restrict__ bias,
                                            int N, int K,
                                            float* __restrict__ Cs, int ldc) {
    const int tc = threadIdx.x & 31;
    const int tr = threadIdx.x >> 5;
    const float* Arow = As + tr * RM * lda;
    float acc[RM][U];
#pragma unroll
    for (int i = 0; i < RM; i++)
#pragma unroll
        for (int u = 0; u < U; u++) acc[i][u] = 0.f;
    for (int k = 0; k < K; k++) {
        float wv[U];
        const float* Wk = W + (size_t)k * N + tc;
#pragma unroll
        for (int u = 0; u < U; u++) wv[u] = Wk[32 * u];
#pragma unroll
        for (int i = 0; i < RM; i++) {
            float xv = Arow[i * lda + k];
#pragma unroll
            for (int u = 0; u < U; u++) acc[i][u] += xv * wv[u];
        }
    }
#pragma unroll
    for (int u = 0; u < U; u++) {
        float b = bias[tc + 32 * u];
#pragma unroll
        for (int i = 0; i < RM; i++) {
            float v = acc[i][u] + b;
            if (RELU) v = fmaxf(v, 0.f);
            Cs[(tr * RM + i) * ldc + tc + 32 * u] = v;
        }
    }
}

__global__ __launch_bounds__(256)
void head_kernel(const float* __restrict__ Ws, const float* __restrict__ bs,
                 const float* __restrict__ Wc1, const float* __restrict__ bc1,
                 const float* __restrict__ Wc2, const float* __restrict__ bc2,
                 const float* __restrict__ Wc3, const float* __restrict__ bc3,
                 float* __restrict__ out) {
    extern __shared__ float sm[];
    float* comb = sm;              // 64 x 160
    float* c1s  = sm + 64 * 160;   // 64 x 64
    const int row0 = blockIdx.x * 64;

    for (int idx = threadIdx.x; idx < 64 * 32; idx += 256) {
        int r = idx >> 5, c4 = idx & 31;
        *(float4*)(comb + r * 160 + c4 * 4) =
            *(const float4*)(g_h3 + (size_t)(row0 + r) * 128 + c4 * 4);
    }
    for (int o = threadIdx.x; o < 64 * 32; o += 256) {
        int r = o >> 5, j = o & 31;
        const float* st = g_stats + (size_t)(row0 + r) * 8;
        float a = bs[j];
#pragma unroll
        for (int k = 0; k < 6; k++) a += st[k] * Ws[k * 32 + j];
        comb[r * 160 + 128 + j] = a;
    }
    __syncthreads();

    gemm_scalar<8, 2, true>(comb, 160, Wc1, bc1, 64, 160, c1s, 64);
    __syncthreads();
    gemm_scalar<8, 1, true>(c1s, 64, Wc2, bc2, 32, 64, comb, 32);
    __syncthreads();

    if (threadIdx.x < 64) {
        const float* cr = comb + threadIdx.x * 32;
        float z = bc3[0];
#pragma unroll
        for (int k = 0; k < 32; k++) z += cr[k] * Wc3[k];
        out[row0 + threadIdx.x] = 1.0f / (1.0f + expf(-z));
    }
}

// ---------------- launch ---------------------------------------------------
extern "C" void kernel_launch(void* const* d_in, const int* in_sizes, int n_in,
                              void* d_out, int out_size) {
    const float* x   = (const float*)d_in[0];
    const float* W1  = (const float*)d_in[1];
    const float* b1  = (const float*)d_in[2];
    const float* W2  = (const float*)d_in[3];
    const float* b2  = (const float*)d_in[4];
    const float* W3  = (const float*)d_in[5];
    const float* b3  = (const float*)d_in[6];
    const float* Ws  = (const float*)d_in[7];
    const float* bs  = (const float*)d_in[8];
    const float* Wc1 = (const float*)d_in[9];
    const float* bc1 = (const float*)d_in[10];
    const float* Wc2 = (const float*)d_in[11];
    const float* bc2 = (const float*)d_in[12];
    const float* Wc3 = (const float*)d_in[13];
    const float* bc3 = (const float*)d_in[14];
    float* out = (float*)d_out;

    const int SMEM_G12 = 3 * ((256 + 512) * 80);    // 184320
    const int SMEM_G3  = 3 * ((256 + 256) * 80);    // 122880
    const int SMEM_HEAD = (64 * 160 + 64 * 64) * 4;  // 57344

    static bool attr_set = false;
    if (!attr_set) {
        cudaFuncSetAttribute(gemm_hmma_kernel<1>,
                             cudaFuncAttributeMaxDynamicSharedMemorySize, SMEM_G12);
        cudaFuncSetAttribute(gemm_hmma_kernel<2>,
                             cudaFuncAttributeMaxDynamicSharedMemorySize, SMEM_G12);
        cudaFuncSetAttribute(gemm_hmma_kernel<3>,
                             cudaFuncAttributeMaxDynamicSharedMemorySize, SMEM_G3);
        cudaFuncSetAttribute(head_kernel,
                             cudaFuncAttributeMaxDynamicSharedMemorySize, SMEM_HEAD);
        attr_set = true;
    }

    prep_x_kernel<<<MTOT / 8, 256>>>(x);
    prep_w_kernel<<<(WT_TOTAL + 255) / 256, 256>>>(W1, W2, W3);

    dim3 g1(MTOT / 128, 2);   // N=512 in two 256-wide passes
    gemm_hmma_kernel<1><<<g1, 512, SMEM_G12>>>(b1);
    gemm_hmma_kernel<2><<<MTOT / 128, 512, SMEM_G12>>>(b2);
    gemm_hmma_kernel<3><<<MTOT / 128, 512, SMEM_G3>>>(b3);

    head_kernel<<<MTOT / 64, 256, SMEM_HEAD>>>(Ws, bs, Wc1, bc1, Wc2, bc2,
                                               Wc3, bc3, out);
}

// round 7
// speedup vs baseline: 1.4066x; 1.4066x over previous
#include <cuda_runtime.h>
#include <cuda_fp16.h>
#include <math.h>
#include <cstdint>

// ===========================================================================
// Fused MLP via mma.sync HMMA fp16 2-product split:
//   activations: single fp16 (eps ~2^-11); weights: fp16 hi+lo (exact)
//   D = A*Wh + A*Wl  -> 2 MMAs per k16/n8 tile (was 3 with bf16 hi/lo)
//   prep_x : x fp32 -> fp16 [65536,384] (+ row stats)
//   prep_w : W1/W2/W3 -> transposed [N,Kpad] fp16 hi/lo
//   gemm<L>: 512-thr CTA, tile M=128 x N=256 (128 L3), warp 32x64,
//            K-chunk 64, 2-stage cp.async double buffer (round-5 shape).
//   head   : stats@Ws -> concat -> C1,C2,C3 -> sigmoid  (fp32)
// ===========================================================================

#define MTOT 65536

// ---------------- device scratch -------------------------------------------
__device__ __half g_x[(size_t)MTOT * 384];
__device__ __half g_w1h[512 * 384], g_w1l[512 * 384];
__device__ __half g_w2h[256 * 512], g_w2l[256 * 512];
__device__ __half g_w3h[128 * 256], g_w3l[128 * 256];
__device__ __half g_h1[(size_t)MTOT * 512];
__device__ __half g_h2[(size_t)MTOT * 256];
__device__ float g_h3[(size_t)MTOT * 128];
__device__ float g_stats[(size_t)MTOT * 8];

// ---------------- helpers --------------------------------------------------
__device__ __forceinline__ uint32_t smem_to_u32(const void* p) {
    uint32_t a;
    asm("{ .reg .u64 t; cvta.to.shared.u64 t, %1; cvt.u32.u64 %0, t; }"
        : "=r"(a) : "l"(p));
    return a;
}
__device__ __forceinline__ void ldsm4(uint32_t* r, uint32_t addr) {
    asm volatile("ldmatrix.sync.aligned.m8n8.x4.shared.b16 {%0,%1,%2,%3}, [%4];"
        : "=r"(r[0]), "=r"(r[1]), "=r"(r[2]), "=r"(r[3]) : "r"(addr));
}
__device__ __forceinline__ void mma16816(float* c, const uint32_t* a,
                                         const uint32_t* b) {
    asm volatile(
        "mma.sync.aligned.m16n8k16.row.col.f32.f16.f16.f32 "
        "{%0,%1,%2,%3}, {%4,%5,%6,%7}, {%8,%9}, {%0,%1,%2,%3};"
        : "+f"(c[0]), "+f"(c[1]), "+f"(c[2]), "+f"(c[3])
        : "r"(a[0]), "r"(a[1]), "r"(a[2]), "r"(a[3]), "r"(b[0]), "r"(b[1]));
}
__device__ __forceinline__ void cp_async16(uint32_t dst, const void* src) {
    asm volatile("cp.async.cg.shared.global [%0], [%1], 16;"
        :: "r"(dst), "l"(src));
}
#define CP_COMMIT() asm volatile("cp.async.commit_group;" ::: "memory")
#define CP_WAIT(n)  asm volatile("cp.async.wait_group %0;" :: "n"(n) : "memory")

__device__ __forceinline__ void split_fp16(float v, __half& hi, __half& lo) {
    hi = __float2half_rn(v);
    lo = __float2half_rn(v - __half2float(hi));
}
__device__ __forceinline__ uint32_t pack_h2(__half a, __half b) {
    __half2 t; t.x = a; t.y = b;
    return *(uint32_t*)&t;
}

// ---------------- prep_x: x -> fp16 + row stats ----------------------------
__global__ __launch_bounds__(256)
void prep_x_kernel(const float* __restrict__ x) {
    const int warp = threadIdx.x >> 5, lane = threadIdx.x & 31;
    const int r = blockIdx.x * 8 + warp;
    const float* xr = x + (size_t)r * 365;

    float v[12];
    float s = 0.f, mn = 3.4e38f, mx = -3.4e38f;
#pragma unroll
    for (int i = 0; i < 12; i++) {
        int k = lane + 32 * i;
        bool ok = k < 365;
        v[i] = ok ? xr[k] : 0.f;
        if (ok) { s += v[i]; mn = fminf(mn, v[i]); mx = fmaxf(mx, v[i]); }
    }
#pragma unroll
    for (int o = 16; o; o >>= 1) {
        s += __shfl_xor_sync(0xffffffffu, s, o);
        mn = fminf(mn, __shfl_xor_sync(0xffffffffu, mn, o));
        mx = fmaxf(mx, __shfl_xor_sync(0xffffffffu, mx, o));
    }
    const float mu = s * (1.0f / 365.0f);
    float s2 = 0.f, s3 = 0.f, s4 = 0.f;
#pragma unroll
    for (int i = 0; i < 12; i++) {
        int k = lane + 32 * i;
        if (k < 365) {
            float c = v[i] - mu, c2 = c * c;
            s2 += c2; s3 += c2 * c; s4 += c2 * c2;
        }
    }
#pragma unroll
    for (int o = 16; o; o >>= 1) {
        s2 += __shfl_xor_sync(0xffffffffu, s2, o);
        s3 += __shfl_xor_sync(0xffffffffu, s3, o);
        s4 += __shfl_xor_sync(0xffffffffu, s4, o);
    }
    if (lane == 0) {
        float var1 = s2 * (1.0f / 364.0f);
        float sig = sqrtf(var1);
        float m3 = s3 * (1.0f / 365.0f);
        float m4 = s4 * (1.0f / 365.0f);
        float sig2 = sig * sig;
        float* st = g_stats + (size_t)r * 8;
        st[0] = mu; st[1] = sig; st[2] = mn; st[3] = mx;
        st[4] = m3 / (sig * sig2 + 1e-8f);
        st[5] = m4 / (sig2 * sig2 + 1e-8f);
    }
#pragma unroll
    for (int i = 0; i < 12; i++) {
        int k = lane + 32 * i;
        float val = (k < 365) ? v[i] : 0.f;
        g_x[(size_t)r * 384 + k] = __float2half_rn(val);
    }
}

// ---------------- prep_w ----------------------------------------------------
#define W1T_ELEMS (512 * 384)
#define W2T_ELEMS (256 * 512)
#define W3T_ELEMS (128 * 256)
#define WT_TOTAL  (W1T_ELEMS + W2T_ELEMS + W3T_ELEMS)

__global__ __launch_bounds__(256)
void prep_w_kernel(const float* __restrict__ W1, const float* __restrict__ W2,
                   const float* __restrict__ W3) {
    int idx = blockIdx.x * 256 + threadIdx.x;
    if (idx >= WT_TOTAL) return;
    float v; __half hi, lo;
    if (idx < W1T_ELEMS) {
        int n = idx / 384, k = idx % 384;
        v = (k < 365) ? W1[(size_t)k * 512 + n] : 0.f;
        split_fp16(v, hi, lo);
        g_w1h[idx] = hi; g_w1l[idx] = lo;
    } else if (idx < W1T_ELEMS + W2T_ELEMS) {
        int j = idx - W1T_ELEMS;
        int n = j / 512, k = j % 512;
        v = W2[(size_t)k * 256 + n];
        split_fp16(v, hi, lo);
        g_w2h[j] = hi; g_w2l[j] = lo;
    } else {
        int j = idx - W1T_ELEMS - W2T_ELEMS;
        int n = j / 256, k = j % 256;
        v = W3[(size_t)k * 128 + n];
        split_fp16(v, hi, lo);
        g_w3h[j] = hi; g_w3l[j] = lo;
    }
}

// ---------------- HMMA GEMM, fp16 2-product, 2-stage cp.async --------------
template <int LAYER>
__global__ __launch_bounds__(512, 1)
void gemm_hmma_kernel(const float* __restrict__ bias) {
    constexpr int KPAD  = (LAYER == 1) ? 384 : (LAYER == 2) ? 512 : 256;
    constexpr int BLK_N = (LAYER == 3) ? 128 : 256;
    constexpr int OUTLD = (LAYER == 1) ? 512 : (LAYER == 2) ? 256 : 128;
    constexpr int KB    = KPAD / 64;
    constexpr bool HOUT = (LAYER != 3);       // fp16 activations out
    constexpr int LDSB  = 144;                // 64 fp16 + 16B pad
    constexpr int WARP_N = BLK_N / 4;         // 64 or 32
    constexpr int NWT    = WARP_N / 16;       // 4 or 2
    constexpr int NT     = 2 * NWT;

    // per-buffer smem layout (bytes): A single + B hi + B lo
    constexpr uint32_t A_S  = 0;
    constexpr uint32_t B_HI = 128 * LDSB;                 // 18432
    constexpr uint32_t B_LO = B_HI + BLK_N * LDSB;
    constexpr uint32_t SBUF = B_HI + 2 * BLK_N * LDSB;    // 92160 / 55296

    const __half* A_g  = (LAYER == 1) ? g_x   : (LAYER == 2) ? g_h1  : g_h2;
    const __half* Bh_g = (LAYER == 1) ? g_w1h : (LAYER == 2) ? g_w2h : g_w3h;
    const __half* Bl_g = (LAYER == 1) ? g_w1l : (LAYER == 2) ? g_w2l : g_w3l;
    __half* O = (LAYER == 1) ? g_h1 : g_h2;

    extern __shared__ char smem[];
    const uint32_t sb = smem_to_u32(smem);

    const int tid = threadIdx.x, warp = tid >> 5, lane = tid & 31;
    const int row0 = blockIdx.x * 128;
    const int nbase = blockIdx.y * BLK_N;
    const int wm = (warp & 3) * 32;
    const int wn = (warp >> 2) * WARP_N;

    float acc[2][NT][4];
#pragma unroll
    for (int mt = 0; mt < 2; mt++)
#pragma unroll
        for (int t = 0; t < NT; t++)
#pragma unroll
            for (int j = 0; j < 4; j++) acc[mt][t][j] = 0.f;

    const uint32_t a_off = (uint32_t)(wm + (lane & 15)) * LDSB + ((lane >> 4) * 16);
    const uint32_t b_off = (uint32_t)(wn + (lane & 7) + ((lane >> 4) << 3)) * LDSB
                           + (((lane >> 3) & 1) * 16);

    // one 64-K chunk: A = 1024 granules (16B), B hi+lo = BLK_N*8 each
    auto load_chunk = [&](int kb, int buf) {
        const uint32_t bb = sb + (uint32_t)buf * SBUF;
        const size_t abase = (size_t)row0 * KPAD + kb * 64;
#pragma unroll
        for (int it = 0; it < 2; it++) {
            const int idx = tid + it * 512;
            const int r = idx >> 3, g = idx & 7;
            const size_t src = abase + (size_t)r * KPAD + g * 8;
            cp_async16(bb + A_S + r * LDSB + g * 16, A_g + src);
        }
        const size_t bbase = (size_t)nbase * KPAD + kb * 64;
#pragma unroll
        for (int it = 0; it < BLK_N / 64; it++) {
            const int idx = tid + it * 512;
            const int n = idx >> 3, g = idx & 7;
            const size_t src = bbase + (size_t)n * KPAD + g * 8;
            const uint32_t dst = bb + B_HI + n * LDSB + g * 16;
            cp_async16(dst, Bh_g + src);
            cp_async16(dst + (B_LO - B_HI), Bl_g + src);
        }
    };

    load_chunk(0, 0);
    CP_COMMIT();

    for (int kb = 0; kb < KB; kb++) {
        __syncthreads();                      // all warps done with buf (kb+1)&1
        if (kb + 1 < KB) {
            load_chunk(kb + 1, (kb + 1) & 1);
            CP_COMMIT();
            CP_WAIT(1);
        } else {
            CP_WAIT(0);
        }
        __syncthreads();

        const uint32_t bb = sb + (uint32_t)(kb & 1) * SBUF;
#pragma unroll
        for (int ks = 0; ks < 4; ks++) {
            uint32_t ah[2][4];
#pragma unroll
            for (int mt = 0; mt < 2; mt++)
                ldsm4(ah[mt], bb + A_S + a_off + mt * (16 * LDSB) + ks * 32);
#pragma unroll
            for (int t = 0; t < NWT; t++) {
                uint32_t bh[4], bl[4];
                const uint32_t bo = b_off + t * (16 * LDSB) + ks * 32;
                ldsm4(bh, bb + B_HI + bo);
                ldsm4(bl, bb + B_LO + bo);
#pragma unroll
                for (int mt = 0; mt < 2; mt++) {
                    mma16816(acc[mt][2 * t],     ah[mt], bh);
                    mma16816(acc[mt][2 * t + 1], ah[mt], bh + 2);
                    mma16816(acc[mt][2 * t],     ah[mt], bl);
                    mma16816(acc[mt][2 * t + 1], ah[mt], bl + 2);
                }
            }
        }
    }

    // ---- epilogue: bias + relu ----
#pragma unroll
    for (int mt = 0; mt < 2; mt++) {
        const int r0 = row0 + wm + mt * 16 + (lane >> 2);
        const int r1 = r0 + 8;
#pragma unroll
        for (int t = 0; t < NT; t++) {
            const int ncol = wn + t * 8 + (lane & 3) * 2;
            const float b0 = bias[nbase + ncol];
            const float b1 = bias[nbase + ncol + 1];
            float d0 = fmaxf(acc[mt][t][0] + b0, 0.f);
            float d1 = fmaxf(acc[mt][t][1] + b1, 0.f);
            float d2 = fmaxf(acc[mt][t][2] + b0, 0.f);
            float d3 = fmaxf(acc[mt][t][3] + b1, 0.f);
            if (HOUT) {
                *(uint32_t*)(O + (size_t)r0 * OUTLD + nbase + ncol) =
                    pack_h2(__float2half_rn(d0), __float2half_rn(d1));
                *(uint32_t*)(O + (size_t)r1 * OUTLD + nbase + ncol) =
                    pack_h2(__float2half_rn(d2), __float2half_rn(d3));
            } else {
                *(float2*)(g_h3 + (size_t)r0 * OUTLD + nbase + ncol) = make_float2(d0, d1);
                *(float2*)(g_h3 + (size_t)r1 * OUTLD + nbase + ncol) = make_float2(d2, d3);
            }
        }
    }
}

// ---------------- head ------------------------------------------------------
template <int RM, int U, bool RELU>
__device__ __forceinline__ void gemm_scalar(const float* __restrict__ As, int lda,
                                            const float* __restrict__ W,
                                            const float* __restrict__ bias,
                                            int N, int K,
                                            float* __restrict__ Cs, int ldc) {
    const int tc = threadIdx.x & 31;
    const int tr = threadIdx.x >> 5;
    const float* Arow = As + tr * RM * lda;
    float acc[RM][U];
#pragma unroll
    for (int i = 0; i < RM; i++)
#pragma unroll
        for (int u = 0; u < U; u++) acc[i][u] = 0.f;
    for (int k = 0; k < K; k++) {
        float wv[U];
        const float* Wk = W + (size_t)k * N + tc;
#pragma unroll
        for (int u = 0; u < U; u++) wv[u] = Wk[32 * u];
#pragma unroll
        for (int i = 0; i < RM; i++) {
            float xv = Arow[i * lda + k];
#pragma unroll
            for (int u = 0; u < U; u++) acc[i][u] += xv * wv[u];
        }
    }
#pragma unroll
    for (int u = 0; u < U; u++) {
        float b = bias[tc + 32 * u];
#pragma unroll
        for (int i = 0; i < RM; i++) {
            float v = acc[i][u] + b;
            if (RELU) v = fmaxf(v, 0.f);
            Cs[(tr * RM + i) * ldc + tc + 32 * u] = v;
        }
    }
}

__global__ __launch_bounds__(256)
void head_kernel(const float* __restrict__ Ws, const float* __restrict__ bs,
                 const float* __restrict__ Wc1, const float* __restrict__ bc1,
                 const float* __restrict__ Wc2, const float* __restrict__ bc2,
                 const float* __restrict__ Wc3, const float* __restrict__ bc3,
                 float* __restrict__ out) {
    extern __shared__ float sm[];
    float* comb = sm;              // 64 x 160
    float* c1s  = sm + 64 * 160;   // 64 x 64
    const int row0 = blockIdx.x * 64;

    for (int idx = threadIdx.x; idx < 64 * 32; idx += 256) {
        int r = idx >> 5, c4 = idx & 31;
        *(float4*)(comb + r * 160 + c4 * 4) =
            *(const float4*)(g_h3 + (size_t)(row0 + r) * 128 + c4 * 4);
    }
    for (int o = threadIdx.x; o < 64 * 32; o += 256) {
        int r = o >> 5, j = o & 31;
        const float* st = g_stats + (size_t)(row0 + r) * 8;
        float a = bs[j];
#pragma unroll
        for (int k = 0; k < 6; k++) a += st[k] * Ws[k * 32 + j];
        comb[r * 160 + 128 + j] = a;
    }
    __syncthreads();

    gemm_scalar<8, 2, true>(comb, 160, Wc1, bc1, 64, 160, c1s, 64);
    __syncthreads();
    gemm_scalar<8, 1, true>(c1s, 64, Wc2, bc2, 32, 64, comb, 32);
    __syncthreads();

    if (threadIdx.x < 64) {
        const float* cr = comb + threadIdx.x * 32;
        float z = bc3[0];
#pragma unroll
        for (int k = 0; k < 32; k++) z += cr[k] * Wc3[k];
        out[row0 + threadIdx.x] = 1.0f / (1.0f + expf(-z));
    }
}

// ---------------- launch ---------------------------------------------------
extern "C" void kernel_launch(void* const* d_in, const int* in_sizes, int n_in,
                              void* d_out, int out_size) {
    const float* x   = (const float*)d_in[0];
    const float* W1  = (const float*)d_in[1];
    const float* b1  = (const float*)d_in[2];
    const float* W2  = (const float*)d_in[3];
    const float* b2  = (const float*)d_in[4];
    const float* W3  = (const float*)d_in[5];
    const float* b3  = (const float*)d_in[6];
    const float* Ws  = (const float*)d_in[7];
    const float* bs  = (const float*)d_in[8];
    const float* Wc1 = (const float*)d_in[9];
    const float* bc1 = (const float*)d_in[10];
    const float* Wc2 = (const float*)d_in[11];
    const float* bc2 = (const float*)d_in[12];
    const float* Wc3 = (const float*)d_in[13];
    const float* bc3 = (const float*)d_in[14];
    float* out = (float*)d_out;

    const int SMEM_G12 = 2 * ((128 + 512) * 144);   // 184320
    const int SMEM_G3  = 2 * ((128 + 256) * 144);   // 110592
    const int SMEM_HEAD = (64 * 160 + 64 * 64) * 4;  // 57344

    static bool attr_set = false;
    if (!attr_set) {
        cudaFuncSetAttribute(gemm_hmma_kernel<1>,
                             cudaFuncAttributeMaxDynamicSharedMemorySize, SMEM_G12);
        cudaFuncSetAttribute(gemm_hmma_kernel<2>,
                             cudaFuncAttributeMaxDynamicSharedMemorySize, SMEM_G12);
        cudaFuncSetAttribute(gemm_hmma_kernel<3>,
                             cudaFuncAttributeMaxDynamicSharedMemorySize, SMEM_G3);
        cudaFuncSetAttribute(head_kernel,
                             cudaFuncAttributeMaxDynamicSharedMemorySize, SMEM_HEAD);
        attr_set = true;
    }

    prep_x_kernel<<<MTOT / 8, 256>>>(x);
    prep_w_kernel<<<(WT_TOTAL + 255) / 256, 256>>>(W1, W2, W3);

    dim3 g1(MTOT / 128, 2);   // N=512 in two 256-wide passes
    gemm_hmma_kernel<1><<<g1, 512, SMEM_G12>>>(b1);
    gemm_hmma_kernel<2><<<MTOT / 128, 512, SMEM_G12>>>(b2);
    gemm_hmma_kernel<3><<<MTOT / 128, 512, SMEM_G3>>>(b3);

    head_kernel<<<MTOT / 64, 256, SMEM_HEAD>>>(Ws, bs, Wc1, bc1, Wc2, bc2,
                                               Wc3, bc3, out);
}

// round 8
// speedup vs baseline: 2.4405x; 1.7351x over previous
#include <cuda_runtime.h>
#include <cuda_fp16.h>
#include <math.h>
#include <cstdint>

// ===========================================================================
// Fused MLP, all GEMMs on HMMA fp16 single-product (eps 2^-11, measured
// aggregate rel_err ~1e-6 per quantized tensor):
//   prep_x : x fp32 -> fp16 [B,384]; row-stats -> stats@Ws+bs -> comb[:,128:160]
//   prep_w : W1/W2/W3/Wc1 -> transposed fp16
//   gemm<1>: h1 = relu(x@W1+b1)    [B,512] fp16
//   gemm<2>: h2 = relu(h1@W2+b2)   [B,256] fp16
//   gemm<3>: comb[:,0:128] = relu(h2@W3+b3)  fp16
//   head   : C1 on HMMA (K=160) -> C2,C3+sigmoid fp32 in smem
// ===========================================================================

#define MTOT 65536

// ---------------- device scratch -------------------------------------------
__device__ __half g_x[(size_t)MTOT * 384];
__device__ __half g_w1[512 * 384];
__device__ __half g_w2[256 * 512];
__device__ __half g_w3[128 * 256];
__device__ __half g_wc1t[64 * 160];
__device__ __half g_h1[(size_t)MTOT * 512];
__device__ __half g_h2[(size_t)MTOT * 256];
__device__ __half g_comb[(size_t)MTOT * 160];

// ---------------- helpers --------------------------------------------------
__device__ __forceinline__ uint32_t smem_to_u32(const void* p) {
    uint32_t a;
    asm("{ .reg .u64 t; cvta.to.shared.u64 t, %1; cvt.u32.u64 %0, t; }"
        : "=r"(a) : "l"(p));
    return a;
}
__device__ __forceinline__ void ldsm4(uint32_t* r, uint32_t addr) {
    asm volatile("ldmatrix.sync.aligned.m8n8.x4.shared.b16 {%0,%1,%2,%3}, [%4];"
        : "=r"(r[0]), "=r"(r[1]), "=r"(r[2]), "=r"(r[3]) : "r"(addr));
}
__device__ __forceinline__ void mma16816(float* c, const uint32_t* a,
                                         const uint32_t* b) {
    asm volatile(
        "mma.sync.aligned.m16n8k16.row.col.f32.f16.f16.f32 "
        "{%0,%1,%2,%3}, {%4,%5,%6,%7}, {%8,%9}, {%0,%1,%2,%3};"
        : "+f"(c[0]), "+f"(c[1]), "+f"(c[2]), "+f"(c[3])
        : "r"(a[0]), "r"(a[1]), "r"(a[2]), "r"(a[3]), "r"(b[0]), "r"(b[1]));
}
__device__ __forceinline__ void cp_async16(uint32_t dst, const void* src) {
    asm volatile("cp.async.cg.shared.global [%0], [%1], 16;"
        :: "r"(dst), "l"(src));
}
#define CP_COMMIT() asm volatile("cp.async.commit_group;" ::: "memory")
#define CP_WAIT(n)  asm volatile("cp.async.wait_group %0;" :: "n"(n) : "memory")

__device__ __forceinline__ uint32_t pack_h2(__half a, __half b) {
    __half2 t; t.x = a; t.y = b;
    return *(uint32_t*)&t;
}

// ---------------- prep_x: x->fp16, stats proj -> comb ----------------------
__global__ __launch_bounds__(256)
void prep_x_kernel(const float* __restrict__ x,
                   const float* __restrict__ Ws, const float* __restrict__ bs) {
    const int warp = threadIdx.x >> 5, lane = threadIdx.x & 31;
    const int r = blockIdx.x * 8 + warp;
    const float* xr = x + (size_t)r * 365;

    float v[12];
    float s = 0.f, mn = 3.4e38f, mx = -3.4e38f;
#pragma unroll
    for (int i = 0; i < 12; i++) {
        int k = lane + 32 * i;
        bool ok = k < 365;
        v[i] = ok ? xr[k] : 0.f;
        if (ok) { s += v[i]; mn = fminf(mn, v[i]); mx = fmaxf(mx, v[i]); }
    }
#pragma unroll
    for (int o = 16; o; o >>= 1) {
        s += __shfl_xor_sync(0xffffffffu, s, o);
        mn = fminf(mn, __shfl_xor_sync(0xffffffffu, mn, o));
        mx = fmaxf(mx, __shfl_xor_sync(0xffffffffu, mx, o));
    }
    const float mu = s * (1.0f / 365.0f);
    float s2 = 0.f, s3 = 0.f, s4 = 0.f;
#pragma unroll
    for (int i = 0; i < 12; i++) {
        int k = lane + 32 * i;
        if (k < 365) {
            float c = v[i] - mu, c2 = c * c;
            s2 += c2; s3 += c2 * c; s4 += c2 * c2;
        }
    }
#pragma unroll
    for (int o = 16; o; o >>= 1) {
        s2 += __shfl_xor_sync(0xffffffffu, s2, o);
        s3 += __shfl_xor_sync(0xffffffffu, s3, o);
        s4 += __shfl_xor_sync(0xffffffffu, s4, o);
    }
    // all lanes hold the reduced values
    const float var1 = s2 * (1.0f / 364.0f);
    const float sig = sqrtf(var1);
    const float m3 = s3 * (1.0f / 365.0f);
    const float m4 = s4 * (1.0f / 365.0f);
    const float sig2 = sig * sig;
    const float skew = m3 / (sig * sig2 + 1e-8f);
    const float kurt = m4 / (sig2 * sig2 + 1e-8f);

    // stats projection -> comb cols [128,160): lane j computes col j
    {
        const int j = lane;
        float a = bs[j];
        a += mu   * Ws[0 * 32 + j];
        a += sig  * Ws[1 * 32 + j];
        a += mn   * Ws[2 * 32 + j];
        a += mx   * Ws[3 * 32 + j];
        a += skew * Ws[4 * 32 + j];
        a += kurt * Ws[5 * 32 + j];
        g_comb[(size_t)r * 160 + 128 + j] = __float2half_rn(a);
    }
#pragma unroll
    for (int i = 0; i < 12; i++) {
        int k = lane + 32 * i;
        float val = (k < 365) ? v[i] : 0.f;
        g_x[(size_t)r * 384 + k] = __float2half_rn(val);
    }
}

// ---------------- prep_w ----------------------------------------------------
#define W1T_ELEMS (512 * 384)
#define W2T_ELEMS (256 * 512)
#define W3T_ELEMS (128 * 256)
#define WC1T_ELEMS (64 * 160)
#define WT_TOTAL  (W1T_ELEMS + W2T_ELEMS + W3T_ELEMS + WC1T_ELEMS)

__global__ __launch_bounds__(256)
void prep_w_kernel(const float* __restrict__ W1, const float* __restrict__ W2,
                   const float* __restrict__ W3, const float* __restrict__ Wc1) {
    int idx = blockIdx.x * 256 + threadIdx.x;
    if (idx >= WT_TOTAL) return;
    if (idx < W1T_ELEMS) {
        int n = idx / 384, k = idx % 384;
        float v = (k < 365) ? W1[(size_t)k * 512 + n] : 0.f;
        g_w1[idx] = __float2half_rn(v);
    } else if (idx < W1T_ELEMS + W2T_ELEMS) {
        int j = idx - W1T_ELEMS;
        int n = j / 512, k = j % 512;
        g_w2[j] = __float2half_rn(W2[(size_t)k * 256 + n]);
    } else if (idx < W1T_ELEMS + W2T_ELEMS + W3T_ELEMS) {
        int j = idx - W1T_ELEMS - W2T_ELEMS;
        int n = j / 256, k = j % 256;
        g_w3[j] = __float2half_rn(W3[(size_t)k * 128 + n]);
    } else {
        int j = idx - W1T_ELEMS - W2T_ELEMS - W3T_ELEMS;
        int n = j / 160, k = j % 160;
        g_wc1t[j] = __float2half_rn(Wc1[(size_t)k * 64 + n]);
    }
}

// ---------------- HMMA GEMM, fp16 single product, 2-stage cp.async ---------
template <int LAYER>
__global__ __launch_bounds__(512, 1)
void gemm_hmma_kernel(const float* __restrict__ bias) {
    constexpr int KPAD  = (LAYER == 1) ? 384 : (LAYER == 2) ? 512 : 256;
    constexpr int BLK_N = (LAYER == 3) ? 128 : 256;
    constexpr int OUTLD = (LAYER == 1) ? 512 : (LAYER == 2) ? 256 : 160;
    constexpr int KB    = KPAD / 64;
    constexpr int LDSB  = 144;                // 64 fp16 + 16B pad
    constexpr int WARP_N = BLK_N / 4;         // 64 or 32
    constexpr int NWT    = WARP_N / 16;       // 4 or 2
    constexpr int NT     = 2 * NWT;

    constexpr uint32_t A_S  = 0;
    constexpr uint32_t B_S  = 128 * LDSB;                 // 18432
    constexpr uint32_t SBUF = B_S + BLK_N * LDSB;         // 55296 / 36864

    const __half* A_g = (LAYER == 1) ? g_x  : (LAYER == 2) ? g_h1 : g_h2;
    const __half* B_g = (LAYER == 1) ? g_w1 : (LAYER == 2) ? g_w2 : g_w3;
    __half* O = (LAYER == 1) ? g_h1 : (LAYER == 2) ? g_h2 : g_comb;

    extern __shared__ char smem[];
    const uint32_t sb = smem_to_u32(smem);

    const int tid = threadIdx.x, warp = tid >> 5, lane = tid & 31;
    const int row0 = blockIdx.x * 128;
    const int nbase = blockIdx.y * BLK_N;
    const int wm = (warp & 3) * 32;
    const int wn = (warp >> 2) * WARP_N;

    float acc[2][NT][4];
#pragma unroll
    for (int mt = 0; mt < 2; mt++)
#pragma unroll
        for (int t = 0; t < NT; t++)
#pragma unroll
            for (int j = 0; j < 4; j++) acc[mt][t][j] = 0.f;

    const uint32_t a_off = (uint32_t)(wm + (lane & 15)) * LDSB + ((lane >> 4) * 16);
    const uint32_t b_off = (uint32_t)(wn + (lane & 7) + ((lane >> 4) << 3)) * LDSB
                           + (((lane >> 3) & 1) * 16);

    auto load_chunk = [&](int kb, int buf) {
        const uint32_t bb = sb + (uint32_t)buf * SBUF;
        const size_t abase = (size_t)row0 * KPAD + kb * 64;
#pragma unroll
        for (int it = 0; it < 2; it++) {
            const int idx = tid + it * 512;
            const int r = idx >> 3, g = idx & 7;
            const size_t src = abase + (size_t)r * KPAD + g * 8;
            cp_async16(bb + A_S + r * LDSB + g * 16, A_g + src);
        }
        const size_t bbase = (size_t)nbase * KPAD + kb * 64;
#pragma unroll
        for (int it = 0; it < BLK_N / 64; it++) {
            const int idx = tid + it * 512;
            const int n = idx >> 3, g = idx & 7;
            const size_t src = bbase + (size_t)n * KPAD + g * 8;
            cp_async16(bb + B_S + n * LDSB + g * 16, B_g + src);
        }
    };

    load_chunk(0, 0);
    CP_COMMIT();

    for (int kb = 0; kb < KB; kb++) {
        __syncthreads();
        if (kb + 1 < KB) {
            load_chunk(kb + 1, (kb + 1) & 1);
            CP_COMMIT();
            CP_WAIT(1);
        } else {
            CP_WAIT(0);
        }
        __syncthreads();

        const uint32_t bb = sb + (uint32_t)(kb & 1) * SBUF;
#pragma unroll
        for (int ks = 0; ks < 4; ks++) {
            uint32_t ah[2][4];
#pragma unroll
            for (int mt = 0; mt < 2; mt++)
                ldsm4(ah[mt], bb + A_S + a_off + mt * (16 * LDSB) + ks * 32);
#pragma unroll
            for (int t = 0; t < NWT; t++) {
                uint32_t bh[4];
                ldsm4(bh, bb + B_S + b_off + t * (16 * LDSB) + ks * 32);
#pragma unroll
                for (int mt = 0; mt < 2; mt++) {
                    mma16816(acc[mt][2 * t],     ah[mt], bh);
                    mma16816(acc[mt][2 * t + 1], ah[mt], bh + 2);
                }
            }
        }
    }

    // ---- epilogue: bias + relu -> fp16 ----
#pragma unroll
    for (int mt = 0; mt < 2; mt++) {
        const int r0 = row0 + wm + mt * 16 + (lane >> 2);
        const int r1 = r0 + 8;
#pragma unroll
        for (int t = 0; t < NT; t++) {
            const int ncol = wn + t * 8 + (lane & 3) * 2;
            const float b0 = bias[nbase + ncol];
            const float b1 = bias[nbase + ncol + 1];
            float d0 = fmaxf(acc[mt][t][0] + b0, 0.f);
            float d1 = fmaxf(acc[mt][t][1] + b1, 0.f);
            float d2 = fmaxf(acc[mt][t][2] + b0, 0.f);
            float d3 = fmaxf(acc[mt][t][3] + b1, 0.f);
            *(uint32_t*)(O + (size_t)r0 * OUTLD + nbase + ncol) =
                pack_h2(__float2half_rn(d0), __float2half_rn(d1));
            *(uint32_t*)(O + (size_t)r1 * OUTLD + nbase + ncol) =
                pack_h2(__float2half_rn(d2), __float2half_rn(d3));
        }
    }
}

// ---------------- head: C1 on HMMA (K=160), C2/C3 fp32 in smem -------------
// 256 thr, M-tile 128, N=64. Warp grid 4(m) x 2(n); warp tile 32x32.
__global__ __launch_bounds__(256, 1)
void head_kernel(const float* __restrict__ bc1,
                 const float* __restrict__ Wc2, const float* __restrict__ bc2,
                 const float* __restrict__ Wc3, const float* __restrict__ bc3,
                 float* __restrict__ out) {
    constexpr int LDSB = 336;                 // 160 fp16 (320B) + 16B pad
    constexpr uint32_t COMB = 0;              // 128 x 336 = 43008
    constexpr uint32_t WC1  = 43008;          // 64 x 336  = 21504
    constexpr uint32_t C1S  = 64512;          // 128 x 65 fp32 = 33280
    constexpr uint32_t WC2S = 97792;          // 64 x 32 fp32 = 8192
    constexpr uint32_t WC3S = 105984;         // 32 fp32
    // C2 result reuses COMB region (after barrier), stride 33 floats

    extern __shared__ char smem[];
    const uint32_t sb = smem_to_u32(smem);
    float* smf = (float*)smem;

    const int tid = threadIdx.x, warp = tid >> 5, lane = tid & 31;
    const int row0 = blockIdx.x * 128;
    const int wm = (warp & 3) * 32;
    const int wn = (warp >> 2) * 32;

    // ---- async loads: comb tile, Wc1T, Wc2, Wc3 ----
    for (int i = tid; i < 2560; i += 256) {           // comb: 128 rows x 20 gran
        int r = i / 20, g = i % 20;
        cp_async16(sb + COMB + r * LDSB + g * 16,
                   g_comb + (size_t)(row0 + r) * 160 + g * 8);
    }
    for (int i = tid; i < 1280; i += 256) {           // Wc1T: 64 rows x 20 gran
        int r = i / 20, g = i % 20;
        cp_async16(sb + WC1 + r * LDSB + g * 16, g_wc1t + r * 160 + g * 8);
    }
    for (int i = tid; i < 512; i += 256)              // Wc2: 2048 floats
        cp_async16(sb + WC2S + i * 16, Wc2 + i * 4);
    if (tid < 8)                                      // Wc3: 32 floats
        cp_async16(sb + WC3S + tid * 16, Wc3 + tid * 4);
    CP_COMMIT();
    CP_WAIT(0);
    __syncthreads();

    // ---- C1: HMMA over K=160 ----
    float acc[2][4][4];
#pragma unroll
    for (int mt = 0; mt < 2; mt++)
#pragma unroll
        for (int t = 0; t < 4; t++)
#pragma unroll
            for (int j = 0; j < 4; j++) acc[mt][t][j] = 0.f;

    const uint32_t a_off = (uint32_t)(wm + (lane & 15)) * LDSB + ((lane >> 4) * 16);
    const uint32_t b_off = (uint32_t)(wn + (lane & 7) + ((lane >> 4) << 3)) * LDSB
                           + (((lane >> 3) & 1) * 16);
#pragma unroll
    for (int ks = 0; ks < 10; ks++) {
        uint32_t ah[2][4];
#pragma unroll
        for (int mt = 0; mt < 2; mt++)
            ldsm4(ah[mt], sb + COMB + a_off + mt * (16 * LDSB) + ks * 32);
#pragma unroll
        for (int t = 0; t < 2; t++) {
            uint32_t bh[4];
            ldsm4(bh, sb + WC1 + b_off + t * (16 * LDSB) + ks * 32);
#pragma unroll
            for (int mt = 0; mt < 2; mt++) {
                mma16816(acc[mt][2 * t],     ah[mt], bh);
                mma16816(acc[mt][2 * t + 1], ah[mt], bh + 2);
            }
        }
    }
    // epilogue C1 -> smem c1s (stride 65 floats), relu + bias
    float* c1s = smf + C1S / 4;
#pragma unroll
    for (int mt = 0; mt < 2; mt++) {
        const int r0 = wm + mt * 16 + (lane >> 2);
        const int r1 = r0 + 8;
#pragma unroll
        for (int t = 0; t < 4; t++) {
            const int ncol = wn + t * 8 + (lane & 3) * 2;
            const float b0 = bc1[ncol], b1 = bc1[ncol + 1];
            c1s[r0 * 65 + ncol]     = fmaxf(acc[mt][t][0] + b0, 0.f);
            c1s[r0 * 65 + ncol + 1] = fmaxf(acc[mt][t][1] + b1, 0.f);
            c1s[r1 * 65 + ncol]     = fmaxf(acc[mt][t][2] + b0, 0.f);
            c1s[r1 * 65 + ncol + 1] = fmaxf(acc[mt][t][3] + b1, 0.f);
        }
    }
    __syncthreads();

    // ---- C2: [128,64]@[64,32] fp32 from smem ----
    // thread: row r = tid>>1, 16 cols starting (tid&1)*16
    float* wc2s = smf + WC2S / 4;
    float* c2s  = smf;                       // reuse COMB region, stride 33
    {
        const int r = tid >> 1;
        const int j0 = (tid & 1) * 16;
        float a[16];
#pragma unroll
        for (int j = 0; j < 16; j++) a[j] = bc2[j0 + j];
        const float* c1r = c1s + r * 65;
        for (int k = 0; k < 64; k++) {
            const float v = c1r[k];
            const float* w = wc2s + k * 32 + j0;
#pragma unroll
            for (int j = 0; j < 16; j++) a[j] += v * w[j];
        }
        float* c2r = c2s + r * 33;
#pragma unroll
        for (int j = 0; j < 16; j++) c2r[j0 + j] = fmaxf(a[j], 0.f);
    }
    __syncthreads();

    // ---- C3 + sigmoid ----
    if (tid < 128) {
        const float* c2r = c2s + tid * 33;
        const float* w3 = smf + WC3S / 4;
        float z = bc3[0];
#pragma unroll
        for (int k = 0; k < 32; k++) z += c2r[k] * w3[k];
        out[row0 + tid] = 1.0f / (1.0f + expf(-z));
    }
}

// ---------------- launch ---------------------------------------------------
extern "C" void kernel_launch(void* const* d_in, const int* in_sizes, int n_in,
                              void* d_out, int out_size) {
    const float* x   = (const float*)d_in[0];
    const float* W1  = (const float*)d_in[1];
    const float* b1  = (const float*)d_in[2];
    const float* W2  = (const float*)d_in[3];
    const float* b2  = (const float*)d_in[4];
    const float* W3  = (const float*)d_in[5];
    const float* b3  = (const float*)d_in[6];
    const float* Ws  = (const float*)d_in[7];
    const float* bs  = (const float*)d_in[8];
    const float* Wc1 = (const float*)d_in[9];
    const float* bc1 = (const float*)d_in[10];
    const float* Wc2 = (const float*)d_in[11];
    const float* bc2 = (const float*)d_in[12];
    const float* Wc3 = (const float*)d_in[13];
    const float* bc3 = (const float*)d_in[14];
    float* out = (float*)d_out;

    const int SMEM_G12 = 2 * ((128 + 256) * 144);   // 110592
    const int SMEM_G3  = 2 * ((128 + 128) * 144);   // 73728
    const int SMEM_HEAD = 106112;

    static bool attr_set = false;
    if (!attr_set) {
        cudaFuncSetAttribute(gemm_hmma_kernel<1>,
                             cudaFuncAttributeMaxDynamicSharedMemorySize, SMEM_G12);
        cudaFuncSetAttribute(gemm_hmma_kernel<2>,
                             cudaFuncAttributeMaxDynamicSharedMemorySize, SMEM_G12);
        cudaFuncSetAttribute(gemm_hmma_kernel<3>,
                             cudaFuncAttributeMaxDynamicSharedMemorySize, SMEM_G3);
        cudaFuncSetAttribute(head_kernel,
                             cudaFuncAttributeMaxDynamicSharedMemorySize, SMEM_HEAD);
        attr_set = true;
    }

    prep_x_kernel<<<MTOT / 8, 256>>>(x, Ws, bs);
    prep_w_kernel<<<(WT_TOTAL + 255) / 256, 256>>>(W1, W2, W3, Wc1);

    dim3 g1(MTOT / 128, 2);   // N=512 in two 256-wide passes
    gemm_hmma_kernel<1><<<g1, 512, SMEM_G12>>>(b1);
    gemm_hmma_kernel<2><<<MTOT / 128, 512, SMEM_G12>>>(b2);
    gemm_hmma_kernel<3><<<MTOT / 128, 512, SMEM_G3>>>(b3);

    head_kernel<<<MTOT / 128, 256, SMEM_HEAD>>>(bc1, Wc2, bc2, Wc3, bc3, out);
}